// round 2
// baseline (speedup 1.0000x reference)
#include <cuda_runtime.h>
#include <cuda_bf16.h>
#include <math.h>

// Problem shape
#define BATCH 512
#define SEQ   256
#define DIM   512
#define NORM  0.044194173824159216f   // 1/sqrt(512)

// Packed f32x2 FMA: d = a*b + d (elementwise on 2 floats in a 64-bit reg)
#define FFMA2(d, a, b) \
    asm("fma.rn.f32x2 %0, %1, %2, %3;" : "=l"(d) : "l"(a), "l"(b), "l"(d))
#define UNPK2(lo, hi, v) \
    asm("mov.b64 {%0, %1}, %2;" : "=f"(lo), "=f"(hi) : "l"(v))

// Scratch (static __device__ — no dynamic allocation allowed)
__device__ float g_M[DIM * DIM];                         // norm * Wq @ Wk^T
__device__ float g_G[(size_t)BATCH * SEQ * DIM];         // X @ M   (256 MB)
__device__ float g_Y2[(size_t)BATCH * 2 * DIM];          // per-half y contributions

// ---------------------------------------------------------------------------
// Kernel A: M = norm * (Wq @ Wk^T).
// ---------------------------------------------------------------------------
__global__ void __launch_bounds__(1024) wqwk_kernel(const float* __restrict__ Wq,
                                                    const float* __restrict__ Wk)
{
    __shared__ float aq[32][33];
    __shared__ float ak[32][33];
    int tx = threadIdx.x, ty = threadIdx.y;
    int row = blockIdx.y * 32 + ty;
    int col = blockIdx.x * 32 + tx;
    float acc = 0.0f;
    for (int kt = 0; kt < DIM; kt += 32) {
        aq[ty][tx] = Wq[row * DIM + kt + tx];
        ak[ty][tx] = Wk[(blockIdx.x * 32 + ty) * DIM + kt + tx];
        __syncthreads();
#pragma unroll
        for (int k = 0; k < 32; k++)
            acc += aq[ty][k] * ak[tx][k];
        __syncthreads();
    }
    g_M[row * DIM + col] = acc * NORM;
}

// ---------------------------------------------------------------------------
// Kernel B: G = Xflat @ M.   [131072,512] x [512,512] fp32 SGEMM, f32x2 path.
// BM=128, BN=128, BK=16, 256 threads, 8x8 microtile held as 8x4 f32x2 pairs.
// A stored DUPLICATED in smem so broadcast pairs load directly as f32x2.
// ---------------------------------------------------------------------------
__global__ void __launch_bounds__(256) gemm_G_kernel(const float* __restrict__ A,
                                                     float* __restrict__ C)
{
    const int K = DIM;
    __shared__ float Asd[16][260];   // [k][2*row(+1)] duplicated, padded
    __shared__ float Bs[16][132];    // [k][col], padded

    int tid = threadIdx.x;
    int cCol = blockIdx.x;           // 0..3
    int cRow = blockIdx.y;           // 0..1023

    const float* Ab = A + (size_t)cRow * 128 * K;
    const float* Bb = g_M + cCol * 128;
    float*       Cb = C + (size_t)cRow * 128 * DIM + cCol * 128;

    // global->smem mapping
    int arow = tid >> 1;             // 0..127
    int acol = (tid & 1) * 8;        // 0 or 8
    int brow = tid >> 5;             // 0..7  (also +8)
    int bcol = (tid & 31) * 4;       // 0..124
    // compute mapping
    int tr = tid >> 4;               // 0..15 -> rows tr*8..+7
    int tc = tid & 15;               // 0..15 -> cols tc*8..+7

    unsigned long long acc2[8][4];
#pragma unroll
    for (int i = 0; i < 8; i++)
#pragma unroll
        for (int j = 0; j < 4; j++) acc2[i][j] = 0ULL;

    for (int kt = 0; kt < K; kt += 16) {
        // load A tile (duplicated store)
        float4 a0 = *(const float4*)(Ab + (size_t)arow * K + kt + acol);
        float4 a1 = *(const float4*)(Ab + (size_t)arow * K + kt + acol + 4);
        {
            float av[8] = {a0.x, a0.y, a0.z, a0.w, a1.x, a1.y, a1.z, a1.w};
#pragma unroll
            for (int j = 0; j < 8; j++) {
                float2 d2 = make_float2(av[j], av[j]);
                *(float2*)(&Asd[acol + j][2 * arow]) = d2;
            }
        }
        // load B tile
        *(float4*)(&Bs[brow][bcol]) =
            *(const float4*)(Bb + (size_t)(kt + brow) * DIM + bcol);
        *(float4*)(&Bs[brow + 8][bcol]) =
            *(const float4*)(Bb + (size_t)(kt + brow + 8) * DIM + bcol);
        __syncthreads();

#pragma unroll
        for (int k = 0; k < 16; k++) {
            ulonglong2 av01 = *(const ulonglong2*)(&Asd[k][tr * 16]);
            ulonglong2 av23 = *(const ulonglong2*)(&Asd[k][tr * 16 + 4]);
            ulonglong2 av45 = *(const ulonglong2*)(&Asd[k][tr * 16 + 8]);
            ulonglong2 av67 = *(const ulonglong2*)(&Asd[k][tr * 16 + 12]);
            ulonglong2 bv01 = *(const ulonglong2*)(&Bs[k][tc * 8]);
            ulonglong2 bv23 = *(const ulonglong2*)(&Bs[k][tc * 8 + 4]);
            unsigned long long a2[8] = {av01.x, av01.y, av23.x, av23.y,
                                        av45.x, av45.y, av67.x, av67.y};
            unsigned long long b2[4] = {bv01.x, bv01.y, bv23.x, bv23.y};
#pragma unroll
            for (int i = 0; i < 8; i++) {
                FFMA2(acc2[i][0], a2[i], b2[0]);
                FFMA2(acc2[i][1], a2[i], b2[1]);
                FFMA2(acc2[i][2], a2[i], b2[2]);
                FFMA2(acc2[i][3], a2[i], b2[3]);
            }
        }
        __syncthreads();
    }

#pragma unroll
    for (int i = 0; i < 8; i++) {
        float v[8];
        UNPK2(v[0], v[1], acc2[i][0]);
        UNPK2(v[2], v[3], acc2[i][1]);
        UNPK2(v[4], v[5], acc2[i][2]);
        UNPK2(v[6], v[7], acc2[i][3]);
        *(float4*)(Cb + (size_t)(tr * 8 + i) * DIM + tc * 8) =
            make_float4(v[0], v[1], v[2], v[3]);
        *(float4*)(Cb + (size_t)(tr * 8 + i) * DIM + tc * 8 + 4) =
            make_float4(v[4], v[5], v[6], v[7]);
    }
}

// ---------------------------------------------------------------------------
// Kernel C: per (batch, half) fused, f32x2 path:
//   S[128x256] = G_chunk @ X_b^T ; row softmax ; w_part = colsum(attn) ;
//   y_part[d]  = sum_m w_part[m] * X_b[m,d]  -> g_Y2[(2b+half)*512 + d]
// 512 threads: warp w owns rows w*8..+7, lane owns cols lane*8..+7
// ---------------------------------------------------------------------------
__global__ void __launch_bounds__(512) attn_kernel(const float* __restrict__ X,
                                                   float* __restrict__ Y2)
{
    int bx   = blockIdx.x;        // 0..1023
    int b    = bx >> 1;
    int half = bx & 1;
    int tid  = threadIdx.x;
    int warp = tid >> 5;
    int lane = tid & 31;

    __shared__ float Gsd[16][260];   // duplicated G rows: [k][2r(+1)]
    __shared__ float Xs[16][260];    // [k][m], 256 cols padded
    __shared__ float wpart[16][256];
    __shared__ float w_s[256];

    const float* Gb = g_G + ((size_t)b * SEQ + half * 128) * DIM;
    const float* Xb = X + (size_t)b * SEQ * DIM;

    unsigned long long acc2[8][4];
#pragma unroll
    for (int i = 0; i < 8; i++)
#pragma unroll
        for (int j = 0; j < 4; j++) acc2[i][j] = 0ULL;

    int gr = tid >> 2;            // 0..127
    int gk = (tid & 3) * 4;       // 0,4,8,12
    int xm = tid >> 1;            // 0..255
    int xk = (tid & 1) * 8;       // 0 or 8
    int c0 = lane * 8;            // cols for compute

    for (int kt = 0; kt < DIM; kt += 16) {
        // G tile, duplicated store
        {
            float4 g4 = *(const float4*)(Gb + (size_t)gr * DIM + kt + gk);
            float gv[4] = {g4.x, g4.y, g4.z, g4.w};
#pragma unroll
            for (int j = 0; j < 4; j++)
                *(float2*)(&Gsd[gk + j][2 * gr]) = make_float2(gv[j], gv[j]);
        }
        // X tile (transposed into [k][m])
        {
            float4 xa = *(const float4*)(Xb + (size_t)xm * DIM + kt + xk);
            float4 xb4 = *(const float4*)(Xb + (size_t)xm * DIM + kt + xk + 4);
            Xs[xk + 0][xm] = xa.x;
            Xs[xk + 1][xm] = xa.y;
            Xs[xk + 2][xm] = xa.z;
            Xs[xk + 3][xm] = xa.w;
            Xs[xk + 4][xm] = xb4.x;
            Xs[xk + 5][xm] = xb4.y;
            Xs[xk + 6][xm] = xb4.z;
            Xs[xk + 7][xm] = xb4.w;
        }
        __syncthreads();

#pragma unroll
        for (int k = 0; k < 16; k++) {
            ulonglong2 gv01 = *(const ulonglong2*)(&Gsd[k][warp * 16]);
            ulonglong2 gv23 = *(const ulonglong2*)(&Gsd[k][warp * 16 + 4]);
            ulonglong2 gv45 = *(const ulonglong2*)(&Gsd[k][warp * 16 + 8]);
            ulonglong2 gv67 = *(const ulonglong2*)(&Gsd[k][warp * 16 + 12]);
            ulonglong2 xv01 = *(const ulonglong2*)(&Xs[k][c0]);
            ulonglong2 xv23 = *(const ulonglong2*)(&Xs[k][c0 + 4]);
            unsigned long long a2[8] = {gv01.x, gv01.y, gv23.x, gv23.y,
                                        gv45.x, gv45.y, gv67.x, gv67.y};
            unsigned long long b2[4] = {xv01.x, xv01.y, xv23.x, xv23.y};
#pragma unroll
            for (int i = 0; i < 8; i++) {
                FFMA2(acc2[i][0], a2[i], b2[0]);
                FFMA2(acc2[i][1], a2[i], b2[1]);
                FFMA2(acc2[i][2], a2[i], b2[2]);
                FFMA2(acc2[i][3], a2[i], b2[3]);
            }
        }
        __syncthreads();
    }

    // Row softmax + column-sum accumulation (each warp handles its 8 rows)
    float colacc[8];
#pragma unroll
    for (int j = 0; j < 8; j++) colacc[j] = 0.0f;

#pragma unroll
    for (int i = 0; i < 8; i++) {
        float s[8];
        UNPK2(s[0], s[1], acc2[i][0]);
        UNPK2(s[2], s[3], acc2[i][1]);
        UNPK2(s[4], s[5], acc2[i][2]);
        UNPK2(s[6], s[7], acc2[i][3]);
        float rmax = s[0];
#pragma unroll
        for (int j = 1; j < 8; j++) rmax = fmaxf(rmax, s[j]);
#pragma unroll
        for (int o = 16; o > 0; o >>= 1)
            rmax = fmaxf(rmax, __shfl_xor_sync(0xffffffffu, rmax, o));
        float e[8], rsum = 0.0f;
#pragma unroll
        for (int j = 0; j < 8; j++) {
            e[j] = __expf(s[j] - rmax);
            rsum += e[j];
        }
#pragma unroll
        for (int o = 16; o > 0; o >>= 1)
            rsum += __shfl_xor_sync(0xffffffffu, rsum, o);
        float inv = 1.0f / rsum;
#pragma unroll
        for (int j = 0; j < 8; j++) colacc[j] += e[j] * inv;
    }
#pragma unroll
    for (int j = 0; j < 8; j++) wpart[warp][c0 + j] = colacc[j];
    __syncthreads();

    if (tid < 256) {
        float s = 0.0f;
#pragma unroll
        for (int w = 0; w < 16; w++) s += wpart[w][tid];
        w_s[tid] = s;
    }
    __syncthreads();

    // y_part[d] = sum_m w_s[m] * X_b[m, d]
    {
        int d = tid;               // 0..511
        float y = 0.0f;
#pragma unroll 4
        for (int m = 0; m < SEQ; m++)
            y = fmaf(w_s[m], Xb[(size_t)m * DIM + d], y);
        Y2[(size_t)bx * DIM + d] = y;
    }
}

// ---------------------------------------------------------------------------
// Kernel D: merged = Y @ Wv, where Y[b] = Y2[2b] + Y2[2b+1]
// ---------------------------------------------------------------------------
__global__ void __launch_bounds__(1024) final_gemm_kernel(const float* __restrict__ Wv,
                                                          float* __restrict__ out)
{
    __shared__ float ys[32][33];
    __shared__ float ws[32][33];
    int tx = threadIdx.x, ty = threadIdx.y;
    int row = blockIdx.y * 32 + ty;      // batch
    int col = blockIdx.x * 32 + tx;      // output dim
    float acc = 0.0f;
    for (int kt = 0; kt < DIM; kt += 32) {
        ys[ty][tx] = g_Y2[(size_t)(2 * row) * DIM + kt + tx] +
                     g_Y2[(size_t)(2 * row + 1) * DIM + kt + tx];
        ws[ty][tx] = Wv[(size_t)(kt + ty) * DIM + col];
        __syncthreads();
#pragma unroll
        for (int k = 0; k < 32; k++)
            acc += ys[ty][k] * ws[k][tx];
        __syncthreads();
    }
    out[(size_t)row * DIM + col] = acc;
}

// ---------------------------------------------------------------------------
// Launch
// ---------------------------------------------------------------------------
extern "C" void kernel_launch(void* const* d_in, const int* in_sizes, int n_in,
                              void* d_out, int out_size)
{
    const float* X  = (const float*)d_in[0];   // [512,256,512]
    const float* Wq = (const float*)d_in[1];   // [512,512]
    const float* Wk = (const float*)d_in[2];
    const float* Wv = (const float*)d_in[3];
    float* out = (float*)d_out;                // [512,512]

    float* G;
    float* Y2;
    cudaGetSymbolAddress((void**)&G,  g_G);
    cudaGetSymbolAddress((void**)&Y2, g_Y2);

    // A: M = norm * Wq @ Wk^T
    wqwk_kernel<<<dim3(16, 16), dim3(32, 32)>>>(Wq, Wk);
    // B: G = Xflat @ M
    gemm_G_kernel<<<dim3(4, 1024), 256>>>(X, G);
    // C: fused scores/softmax/colsum/y per (batch, half)
    attn_kernel<<<1024, 512>>>(X, Y2);
    // D: merged = (Y2[2b]+Y2[2b+1]) @ Wv
    final_gemm_kernel<<<dim3(16, 16), dim3(32, 32)>>>(Wv, out);
}

// round 3
// speedup vs baseline: 2.6858x; 2.6858x over previous
#include <cuda_runtime.h>
#include <cuda_bf16.h>
#include <math.h>

// Problem shape
#define BATCH 512
#define SEQ   256
#define DIM   512
#define NORM  0.044194173824159216f   // 1/sqrt(512)

// Scratch (static __device__ — no dynamic allocation allowed)
__device__ float g_M[DIM * DIM];                         // norm * Wq @ Wk^T
__device__ float g_G[(size_t)BATCH * SEQ * DIM];         // X @ M   (256 MB)
__device__ float g_Y2[(size_t)BATCH * 2 * DIM];          // per-half y contributions

// ---------------------------------------------------------------------------
// tf32 helpers
// ---------------------------------------------------------------------------
__device__ __forceinline__ unsigned f2tf32(float f) {
    unsigned u;
    asm("cvt.rna.tf32.f32 %0, %1;" : "=r"(u) : "f"(f));
    return u;
}
__device__ __forceinline__ void mma_tf32(float c[4],
                                         unsigned a0, unsigned a1, unsigned a2, unsigned a3,
                                         unsigned b0, unsigned b1) {
    asm("mma.sync.aligned.m16n8k8.row.col.f32.tf32.tf32.f32 "
        "{%0,%1,%2,%3}, {%4,%5,%6,%7}, {%8,%9}, {%0,%1,%2,%3};"
        : "+f"(c[0]), "+f"(c[1]), "+f"(c[2]), "+f"(c[3])
        : "r"(a0), "r"(a1), "r"(a2), "r"(a3), "r"(b0), "r"(b1));
}
__device__ __forceinline__ uint4 cvt4(float4 v) {
    uint4 u;
    u.x = f2tf32(v.x); u.y = f2tf32(v.y); u.z = f2tf32(v.z); u.w = f2tf32(v.w);
    return u;
}

// ---------------------------------------------------------------------------
// Kernel A: M = norm * (Wq @ Wk^T).   (small; kept scalar)
// ---------------------------------------------------------------------------
__global__ void __launch_bounds__(1024) wqwk_kernel(const float* __restrict__ Wq,
                                                    const float* __restrict__ Wk)
{
    __shared__ float aq[32][33];
    __shared__ float ak[32][33];
    int tx = threadIdx.x, ty = threadIdx.y;
    int row = blockIdx.y * 32 + ty;
    int col = blockIdx.x * 32 + tx;
    float acc = 0.0f;
    for (int kt = 0; kt < DIM; kt += 32) {
        aq[ty][tx] = Wq[row * DIM + kt + tx];
        ak[ty][tx] = Wk[(blockIdx.x * 32 + ty) * DIM + kt + tx];
        __syncthreads();
#pragma unroll
        for (int k = 0; k < 32; k++)
            acc += aq[ty][k] * ak[tx][k];
        __syncthreads();
    }
    g_M[row * DIM + col] = acc * NORM;
}

// ---------------------------------------------------------------------------
// Kernel B: G = Xflat @ M via tf32 mma.sync.
// CTA tile 128x128, BK=16, 256 threads = 8 warps (2x4), warp tile 64x32.
// smem strides chosen for conflict-free fragment loads:
//   As stride 20 (20r+c -> bank 4r+c unique), Bs stride 136 (bank 8k+n unique)
// ---------------------------------------------------------------------------
__global__ void __launch_bounds__(256) gemm_G_kernel(const float* __restrict__ A,
                                                     float* __restrict__ C)
{
    __shared__ __align__(16) unsigned As[128][20];
    __shared__ __align__(16) unsigned Bs[16][136];

    int tid  = threadIdx.x;
    int cCol = blockIdx.x;            // 0..3
    int cRow = blockIdx.y;            // 0..1023
    int warp = tid >> 5, lane = tid & 31;
    int wm = warp >> 2, wn = warp & 3;     // warp grid 2 x 4
    int gid = lane >> 2, tig = lane & 3;

    const float* Ab = A + (size_t)cRow * 128 * DIM;
    float*       Cb = C + (size_t)cRow * 128 * DIM + cCol * 128;

    // staging maps
    int sm_  = tid >> 1;              // 0..127
    int skoff = (tid & 1) * 8;        // 0 or 8
    int sk   = tid >> 4;              // 0..15
    int snoff = (tid & 15) * 8;       // 0..120

    float acc[4][4][4];
#pragma unroll
    for (int mt = 0; mt < 4; mt++)
#pragma unroll
        for (int nt = 0; nt < 4; nt++)
#pragma unroll
            for (int r = 0; r < 4; r++) acc[mt][nt][r] = 0.0f;

    for (int kt = 0; kt < DIM; kt += 16) {
        // stage A (X rows), convert to tf32
        float4 a0 = *(const float4*)(Ab + (size_t)sm_ * DIM + kt + skoff);
        float4 a1 = *(const float4*)(Ab + (size_t)sm_ * DIM + kt + skoff + 4);
        *(uint4*)&As[sm_][skoff]     = cvt4(a0);
        *(uint4*)&As[sm_][skoff + 4] = cvt4(a1);
        // stage B (M rows)
        const float* Bp = g_M + (size_t)(kt + sk) * DIM + cCol * 128 + snoff;
        *(uint4*)&Bs[sk][snoff]     = cvt4(*(const float4*)Bp);
        *(uint4*)&Bs[sk][snoff + 4] = cvt4(*(const float4*)(Bp + 4));
        __syncthreads();

#pragma unroll
        for (int k8 = 0; k8 < 2; k8++) {
            int kb = k8 * 8;
            unsigned af[4][4];
#pragma unroll
            for (int mt = 0; mt < 4; mt++) {
                int row = wm * 64 + mt * 16 + gid;
                af[mt][0] = As[row][kb + tig];
                af[mt][1] = As[row + 8][kb + tig];
                af[mt][2] = As[row][kb + tig + 4];
                af[mt][3] = As[row + 8][kb + tig + 4];
            }
            unsigned bf[4][2];
#pragma unroll
            for (int nt = 0; nt < 4; nt++) {
                int col = wn * 32 + nt * 8 + gid;
                bf[nt][0] = Bs[kb + tig][col];
                bf[nt][1] = Bs[kb + tig + 4][col];
            }
#pragma unroll
            for (int mt = 0; mt < 4; mt++)
#pragma unroll
                for (int nt = 0; nt < 4; nt++)
                    mma_tf32(acc[mt][nt], af[mt][0], af[mt][1], af[mt][2], af[mt][3],
                             bf[nt][0], bf[nt][1]);
        }
        __syncthreads();
    }

#pragma unroll
    for (int mt = 0; mt < 4; mt++)
#pragma unroll
        for (int nt = 0; nt < 4; nt++) {
            int r = wm * 64 + mt * 16 + gid;
            int c = wn * 32 + nt * 8 + 2 * tig;
            *(float2*)(Cb + (size_t)r * DIM + c) =
                make_float2(acc[mt][nt][0], acc[mt][nt][1]);
            *(float2*)(Cb + (size_t)(r + 8) * DIM + c) =
                make_float2(acc[mt][nt][2], acc[mt][nt][3]);
        }
}

// ---------------------------------------------------------------------------
// Kernel C: per (batch, half): S = G_half @ X_b^T (tf32 mma), row softmax,
// colsum(attn) -> w, y = w @ X_b.
// 512 threads = 16 warps (4x4), warp tile 32x64 over S[128x256].
// ---------------------------------------------------------------------------
__global__ void __launch_bounds__(512) attn_kernel(const float* __restrict__ X,
                                                   float* __restrict__ Y2)
{
    __shared__ __align__(16) unsigned Gs[128][20];
    __shared__ __align__(16) unsigned Xs[16][264];
    __shared__ float red[128][4];
    __shared__ float wcol[4][256];
    __shared__ float w_s[256];

    int bx   = blockIdx.x;         // 0..1023
    int b    = bx >> 1;
    int half = bx & 1;
    int tid  = threadIdx.x;
    int warp = tid >> 5, lane = tid & 31;
    int wm = warp >> 2, wn = warp & 3;   // 4 x 4
    int gid = lane >> 2, tig = lane & 3;

    const float* Gb = g_G + ((size_t)b * SEQ + half * 128) * DIM;
    const float* Xb = X + (size_t)b * SEQ * DIM;

    // staging maps
    int gm = tid >> 2, gkoff = (tid & 3) * 4;      // G: 128 x 16
    int xn = tid >> 1, xkoff = (tid & 1) * 8;      // X: 256 x 16 (transposed store)

    float acc[2][8][4];
#pragma unroll
    for (int mt = 0; mt < 2; mt++)
#pragma unroll
        for (int nt = 0; nt < 8; nt++)
#pragma unroll
            for (int r = 0; r < 4; r++) acc[mt][nt][r] = 0.0f;

    for (int kt = 0; kt < DIM; kt += 16) {
        float4 g4 = *(const float4*)(Gb + (size_t)gm * DIM + kt + gkoff);
        *(uint4*)&Gs[gm][gkoff] = cvt4(g4);
        float4 x0 = *(const float4*)(Xb + (size_t)xn * DIM + kt + xkoff);
        float4 x1 = *(const float4*)(Xb + (size_t)xn * DIM + kt + xkoff + 4);
        Xs[xkoff + 0][xn] = f2tf32(x0.x);
        Xs[xkoff + 1][xn] = f2tf32(x0.y);
        Xs[xkoff + 2][xn] = f2tf32(x0.z);
        Xs[xkoff + 3][xn] = f2tf32(x0.w);
        Xs[xkoff + 4][xn] = f2tf32(x1.x);
        Xs[xkoff + 5][xn] = f2tf32(x1.y);
        Xs[xkoff + 6][xn] = f2tf32(x1.z);
        Xs[xkoff + 7][xn] = f2tf32(x1.w);
        __syncthreads();

#pragma unroll
        for (int k8 = 0; k8 < 2; k8++) {
            int kb = k8 * 8;
            unsigned af[2][4];
#pragma unroll
            for (int mt = 0; mt < 2; mt++) {
                int row = wm * 32 + mt * 16 + gid;
                af[mt][0] = Gs[row][kb + tig];
                af[mt][1] = Gs[row + 8][kb + tig];
                af[mt][2] = Gs[row][kb + tig + 4];
                af[mt][3] = Gs[row + 8][kb + tig + 4];
            }
            unsigned bf[8][2];
#pragma unroll
            for (int nt = 0; nt < 8; nt++) {
                int col = wn * 64 + nt * 8 + gid;
                bf[nt][0] = Xs[kb + tig][col];
                bf[nt][1] = Xs[kb + tig + 4][col];
            }
#pragma unroll
            for (int mt = 0; mt < 2; mt++)
#pragma unroll
                for (int nt = 0; nt < 8; nt++)
                    mma_tf32(acc[mt][nt], af[mt][0], af[mt][1], af[mt][2], af[mt][3],
                             bf[nt][0], bf[nt][1]);
        }
        __syncthreads();
    }

    // ---------------- softmax epilogue ----------------
    // rows owned by this thread: for mt: r0 = wm*32+mt*16+gid and r0+8
    // Pass 1: row max
    float rm[2][2];
#pragma unroll
    for (int mt = 0; mt < 2; mt++) {
        float m0 = -1e30f, m1 = -1e30f;
#pragma unroll
        for (int nt = 0; nt < 8; nt++) {
            m0 = fmaxf(m0, fmaxf(acc[mt][nt][0], acc[mt][nt][1]));
            m1 = fmaxf(m1, fmaxf(acc[mt][nt][2], acc[mt][nt][3]));
        }
        m0 = fmaxf(m0, __shfl_xor_sync(0xffffffffu, m0, 1));
        m0 = fmaxf(m0, __shfl_xor_sync(0xffffffffu, m0, 2));
        m1 = fmaxf(m1, __shfl_xor_sync(0xffffffffu, m1, 1));
        m1 = fmaxf(m1, __shfl_xor_sync(0xffffffffu, m1, 2));
        rm[mt][0] = m0; rm[mt][1] = m1;
    }
    if (tig == 0) {
#pragma unroll
        for (int mt = 0; mt < 2; mt++) {
            red[wm * 32 + mt * 16 + gid][wn]     = rm[mt][0];
            red[wm * 32 + mt * 16 + gid + 8][wn] = rm[mt][1];
        }
    }
    __syncthreads();
#pragma unroll
    for (int mt = 0; mt < 2; mt++) {
        int r0 = wm * 32 + mt * 16 + gid;
        rm[mt][0] = fmaxf(fmaxf(red[r0][0], red[r0][1]), fmaxf(red[r0][2], red[r0][3]));
        rm[mt][1] = fmaxf(fmaxf(red[r0 + 8][0], red[r0 + 8][1]),
                          fmaxf(red[r0 + 8][2], red[r0 + 8][3]));
    }
    __syncthreads();

    // Pass 2: exp + row sum
    float rs[2][2];
#pragma unroll
    for (int mt = 0; mt < 2; mt++) {
        float s0 = 0.0f, s1 = 0.0f;
#pragma unroll
        for (int nt = 0; nt < 8; nt++) {
            acc[mt][nt][0] = __expf(acc[mt][nt][0] - rm[mt][0]);
            acc[mt][nt][1] = __expf(acc[mt][nt][1] - rm[mt][0]);
            acc[mt][nt][2] = __expf(acc[mt][nt][2] - rm[mt][1]);
            acc[mt][nt][3] = __expf(acc[mt][nt][3] - rm[mt][1]);
            s0 += acc[mt][nt][0] + acc[mt][nt][1];
            s1 += acc[mt][nt][2] + acc[mt][nt][3];
        }
        s0 += __shfl_xor_sync(0xffffffffu, s0, 1);
        s0 += __shfl_xor_sync(0xffffffffu, s0, 2);
        s1 += __shfl_xor_sync(0xffffffffu, s1, 1);
        s1 += __shfl_xor_sync(0xffffffffu, s1, 2);
        rs[mt][0] = s0; rs[mt][1] = s1;
    }
    if (tig == 0) {
#pragma unroll
        for (int mt = 0; mt < 2; mt++) {
            red[wm * 32 + mt * 16 + gid][wn]     = rs[mt][0];
            red[wm * 32 + mt * 16 + gid + 8][wn] = rs[mt][1];
        }
    }
    __syncthreads();
#pragma unroll
    for (int mt = 0; mt < 2; mt++) {
        int r0 = wm * 32 + mt * 16 + gid;
        float s0 = red[r0][0] + red[r0][1] + red[r0][2] + red[r0][3];
        float s1 = red[r0 + 8][0] + red[r0 + 8][1] + red[r0 + 8][2] + red[r0 + 8][3];
        rs[mt][0] = 1.0f / s0;
        rs[mt][1] = 1.0f / s1;
    }

    // normalize + per-thread column partials (sum over this thread's 4 rows)
    float cp[8][2];
#pragma unroll
    for (int nt = 0; nt < 8; nt++) {
        cp[nt][0] = acc[0][nt][0] * rs[0][0] + acc[0][nt][2] * rs[0][1]
                  + acc[1][nt][0] * rs[1][0] + acc[1][nt][2] * rs[1][1];
        cp[nt][1] = acc[0][nt][1] * rs[0][0] + acc[0][nt][3] * rs[0][1]
                  + acc[1][nt][1] * rs[1][0] + acc[1][nt][3] * rs[1][1];
    }
    // reduce over the 8 lanes sharing tig (columns)  -> colsum over warp's 32 rows
#pragma unroll
    for (int nt = 0; nt < 8; nt++) {
#pragma unroll
        for (int o = 4; o < 32; o <<= 1) {
            cp[nt][0] += __shfl_xor_sync(0xffffffffu, cp[nt][0], o);
            cp[nt][1] += __shfl_xor_sync(0xffffffffu, cp[nt][1], o);
        }
    }
    if (gid == 0) {
#pragma unroll
        for (int nt = 0; nt < 8; nt++) {
            wcol[wm][wn * 64 + nt * 8 + 2 * tig]     = cp[nt][0];
            wcol[wm][wn * 64 + nt * 8 + 2 * tig + 1] = cp[nt][1];
        }
    }
    __syncthreads();
    if (tid < 256)
        w_s[tid] = wcol[0][tid] + wcol[1][tid] + wcol[2][tid] + wcol[3][tid];
    __syncthreads();

    // y_part[d] = sum_m w_s[m] * X_b[m, d]
    {
        int d = tid;
        float y = 0.0f;
#pragma unroll 4
        for (int m = 0; m < SEQ; m++)
            y = fmaf(w_s[m], Xb[(size_t)m * DIM + d], y);
        Y2[(size_t)bx * DIM + d] = y;
    }
}

// ---------------------------------------------------------------------------
// Kernel D: merged = Y @ Wv, where Y[b] = Y2[2b] + Y2[2b+1]
// ---------------------------------------------------------------------------
__global__ void __launch_bounds__(1024) final_gemm_kernel(const float* __restrict__ Wv,
                                                          float* __restrict__ out)
{
    __shared__ float ys[32][33];
    __shared__ float ws[32][33];
    int tx = threadIdx.x, ty = threadIdx.y;
    int row = blockIdx.y * 32 + ty;      // batch
    int col = blockIdx.x * 32 + tx;      // output dim
    float acc = 0.0f;
    for (int kt = 0; kt < DIM; kt += 32) {
        ys[ty][tx] = g_Y2[(size_t)(2 * row) * DIM + kt + tx] +
                     g_Y2[(size_t)(2 * row + 1) * DIM + kt + tx];
        ws[ty][tx] = Wv[(size_t)(kt + ty) * DIM + col];
        __syncthreads();
#pragma unroll
        for (int k = 0; k < 32; k++)
            acc += ys[ty][k] * ws[k][tx];
        __syncthreads();
    }
    out[(size_t)row * DIM + col] = acc;
}

// ---------------------------------------------------------------------------
// Launch
// ---------------------------------------------------------------------------
extern "C" void kernel_launch(void* const* d_in, const int* in_sizes, int n_in,
                              void* d_out, int out_size)
{
    const float* X  = (const float*)d_in[0];   // [512,256,512]
    const float* Wq = (const float*)d_in[1];   // [512,512]
    const float* Wk = (const float*)d_in[2];
    const float* Wv = (const float*)d_in[3];
    float* out = (float*)d_out;                // [512,512]

    float* G;
    float* Y2;
    cudaGetSymbolAddress((void**)&G,  g_G);
    cudaGetSymbolAddress((void**)&Y2, g_Y2);

    // A: M = norm * Wq @ Wk^T
    wqwk_kernel<<<dim3(16, 16), dim3(32, 32)>>>(Wq, Wk);
    // B: G = Xflat @ M  (tf32 tensor cores)
    gemm_G_kernel<<<dim3(4, 1024), 256>>>(X, G);
    // C: fused scores/softmax/colsum/y per (batch, half)  (tf32 tensor cores)
    attn_kernel<<<1024, 512>>>(X, Y2);
    // D: merged = (Y2[2b]+Y2[2b+1]) @ Wv
    final_gemm_kernel<<<dim3(16, 16), dim3(32, 32)>>>(Wv, out);
}